// round 15
// baseline (speedup 1.0000x reference)
#include <cuda_runtime.h>
#include <cuda_bf16.h>
#include <cuda_fp16.h>
#include <math.h>
#include <stdint.h>

// Problem constants
#define BSZ   32
#define SEQ   512
#define BS    (BSZ*SEQ)      // 16384
#define DIM   512
#define NHEAD 8
#define NSLOT 112
#define DIMQ  64
#define DIMM  512
#define DIMO  512
#define RADIUS 16.0f

// ---------------- static scratch ----------------
__device__ float g_vnorm[NSLOT * DIMM];
__device__ float g_wfT  [DIMO * (NHEAD*NSLOT)];
__device__ float g_gram [NSLOT * NSLOT];
__device__ float g_rl   [BS];
__device__ float g_nsq  [BS * 4];      // per-(row,xblock) sumsq partials of vp
__device__ float g_invn [BS];          // 1/||vp_row||

// bf16 split-3 buffers (sim path)
__device__ __nv_bfloat16 g_qv3  [(size_t)2 * BS * 1536];
__device__ __nv_bfloat16 g_qvw3 [(size_t)2 * 512 * 1536];
__device__ __nv_bfloat16 g_qp3  [(size_t)NHEAD * BS * 192];
__device__ __nv_bfloat16 g_vp3  [(size_t)BS * 1536];
__device__ __nv_bfloat16 g_keyn3[(size_t)NHEAD * 128 * 192];
__device__ __nv_bfloat16 g_vnorm3[(size_t)128 * 1536];

// fp16 split-2 buffers (post-softmax path)
__device__ __half g_ka2 [(size_t)BS * 1792];
__device__ __half g_va2 [(size_t)BS * 256];
__device__ __half g_wf2 [(size_t)512 * 1792];
__device__ __half g_vpT2[(size_t)512 * 256];

// ---------------- PTX helpers ----------------
__device__ __forceinline__ uint32_t smem_u32(const void* p) {
    uint32_t a;
    asm("{ .reg .u64 t; cvta.to.shared.u64 t, %1; cvt.u32.u64 %0, t; }" : "=r"(a) : "l"(p));
    return a;
}
__device__ __forceinline__ void cp_async16(uint32_t dst, const void* src) {
    asm volatile("cp.async.cg.shared.global [%0], [%1], 16;\n" :: "r"(dst), "l"(src));
}
#define CP_COMMIT() asm volatile("cp.async.commit_group;\n" ::)
#define CP_WAIT(N)  asm volatile("cp.async.wait_group %0;\n" :: "n"(N))

__device__ __forceinline__ void ldsm_x4(uint32_t& r0, uint32_t& r1, uint32_t& r2,
                                        uint32_t& r3, uint32_t addr) {
    asm volatile("ldmatrix.sync.aligned.m8n8.x4.shared.b16 {%0,%1,%2,%3}, [%4];"
                 : "=r"(r0), "=r"(r1), "=r"(r2), "=r"(r3) : "r"(addr));
}
__device__ __forceinline__ void mma_bf16(float* c, uint32_t a0, uint32_t a1,
                                         uint32_t a2, uint32_t a3,
                                         uint32_t b0, uint32_t b1) {
    asm volatile(
        "mma.sync.aligned.m16n8k16.row.col.f32.bf16.bf16.f32 "
        "{%0,%1,%2,%3}, {%4,%5,%6,%7}, {%8,%9}, {%0,%1,%2,%3};"
        : "+f"(c[0]), "+f"(c[1]), "+f"(c[2]), "+f"(c[3])
        : "r"(a0), "r"(a1), "r"(a2), "r"(a3), "r"(b0), "r"(b1));
}
__device__ __forceinline__ void mma_fp16(float* c, uint32_t a0, uint32_t a1,
                                         uint32_t a2, uint32_t a3,
                                         uint32_t b0, uint32_t b1) {
    asm volatile(
        "mma.sync.aligned.m16n8k16.row.col.f32.f16.f16.f32 "
        "{%0,%1,%2,%3}, {%4,%5,%6,%7}, {%8,%9}, {%0,%1,%2,%3};"
        : "+f"(c[0]), "+f"(c[1]), "+f"(c[2]), "+f"(c[3])
        : "r"(a0), "r"(a1), "r"(a2), "r"(a3), "r"(b0), "r"(b1));
}
__device__ __forceinline__ uint32_t sw128(uint32_t off) {
    return off ^ ((off >> 3) & 0x70);
}
__device__ __forceinline__ float warpSum(float v) {
    #pragma unroll
    for (int o = 16; o > 0; o >>= 1) v += __shfl_xor_sync(0xffffffffu, v, o);
    return v;
}
__device__ __forceinline__ float warpMax(float v) {
    #pragma unroll
    for (int o = 16; o > 0; o >>= 1) v = fmaxf(v, __shfl_xor_sync(0xffffffffu, v, o));
    return v;
}
__device__ __forceinline__ float blockSum256(float v, float* sh) {
    int w = threadIdx.x >> 5, l = threadIdx.x & 31;
    float s = warpSum(v);
    if (l == 0) sh[w] = s;
    __syncthreads();
    float t = (threadIdx.x < 8) ? sh[threadIdx.x] : 0.0f;
    if (w == 0) { t = warpSum(t); if (l == 0) sh[0] = t; }
    __syncthreads();
    float r = sh[0];
    __syncthreads();
    return r;
}

// split stores
__device__ __forceinline__ void put_split3bf(__nv_bfloat16* base, int k, int seg, float x) {
    __nv_bfloat16 h = __float2bfloat16(x);
    __nv_bfloat16 l = __float2bfloat16(x - __bfloat162float(h));
    base[k] = h; base[seg + k] = l; base[2 * seg + k] = h;
}
__device__ __forceinline__ void put_split2h(__half* base, int k, int seg, float x) {
    __half h = __float2half(x);
    __half l = __float2half(x - __half2float(h));
    base[k] = h; base[seg + k] = l;
}

// ---------------- warp-MMA GEMM mainloop (CTA 128x128, BK=64, 3-stage pipe) --------------
// 3 stages x 32KB = 96KB; with __launch_bounds__(256,2): 2 CTAs x 96KB = 192KB <= 228KB.
// One __syncthreads per chunk: the top-of-iteration barrier proves all warps finished
// chunk c-1 (whose buffer (c+2)%3 the new load overwrites).
#define WM_SMEM 98304

template<int DT>
__device__ __forceinline__ void gemm_mainloop(
    const uint16_t* __restrict__ A, const uint16_t* __restrict__ B,
    int K2, uint32_t sb, int tid, int lane, int warp_m, int warp_n,
    int m0, int n0, float acc[4][4][4])
{
    const int NC = K2 >> 6;

    auto load_chunk = [&](int c, int bufi) {
        const uint16_t* Ap = A + (long)m0 * K2 + c * 64;
        const uint16_t* Bp = B + (long)n0 * K2 + c * 64;
        uint32_t sa = sb + bufi * 32768;
        uint32_t sB = sa + 16384;
        #pragma unroll
        for (int i = 0; i < 4; i++) {
            int idx = tid + i * 256;
            int row = idx >> 3, c16 = idx & 7;
            uint32_t sw = sw128(row * 128 + c16 * 16);
            cp_async16(sa + sw, Ap + (long)row * K2 + c16 * 8);
            cp_async16(sB + sw, Bp + (long)row * K2 + c16 * 8);
        }
    };

    load_chunk(0, 0);
    CP_COMMIT();
    if (NC > 1) { load_chunk(1, 1); CP_COMMIT(); }

    for (int c = 0; c < NC; c++) {
        if (c + 1 < NC) { CP_WAIT(1); } else { CP_WAIT(0); }
        __syncthreads();
        if (c + 2 < NC) { load_chunk(c + 2, (c + 2) % 3); CP_COMMIT(); }

        const uint32_t sa = sb + (c % 3) * 32768;
        const uint32_t sB = sa + 16384;

        #pragma unroll
        for (int ks = 0; ks < 4; ks++) {
            uint32_t a[4][4];
            #pragma unroll
            for (int mt = 0; mt < 4; mt++) {
                int row = warp_m * 64 + mt * 16 + (lane & 15);
                uint32_t off = (uint32_t)row * 128 + ks * 32 + (lane >> 4) * 16;
                ldsm_x4(a[mt][0], a[mt][1], a[mt][2], a[mt][3], sa + sw128(off));
            }
            uint32_t bf[4][2];
            #pragma unroll
            for (int p = 0; p < 2; p++) {
                int tile_id = lane >> 3;
                int nsub = tile_id >> 1, kch = tile_id & 1;
                int row = warp_n * 32 + p * 16 + nsub * 8 + (lane & 7);
                uint32_t off = (uint32_t)row * 128 + ks * 32 + kch * 16;
                uint32_t r0, r1, r2, r3;
                ldsm_x4(r0, r1, r2, r3, sB + sw128(off));
                bf[p * 2 + 0][0] = r0; bf[p * 2 + 0][1] = r1;
                bf[p * 2 + 1][0] = r2; bf[p * 2 + 1][1] = r3;
            }
            #pragma unroll
            for (int mt = 0; mt < 4; mt++)
                #pragma unroll
                for (int nt = 0; nt < 4; nt++) {
                    if (DT == 0)
                        mma_bf16(acc[mt][nt], a[mt][0], a[mt][1], a[mt][2], a[mt][3],
                                 bf[nt][0], bf[nt][1]);
                    else
                        mma_fp16(acc[mt][nt], a[mt][0], a[mt][1], a[mt][2], a[mt][3],
                                 bf[nt][0], bf[nt][1]);
                }
        }
    }
    __syncthreads();   // protect smem reuse by epilogue (dump_acc)
}

// dump acc to smem fp32 tile [128][128] with +8*row column skew
__device__ __forceinline__ void dump_acc(float* sm, int warp_m, int warp_n, int lane,
                                         float acc[4][4][4])
{
    const int mrow = lane >> 2, nc0 = (lane & 3) * 2;
    #pragma unroll
    for (int mt = 0; mt < 4; mt++) {
        int r0 = warp_m * 64 + mt * 16 + mrow;
        int r1 = r0 + 8;
        #pragma unroll
        for (int nt = 0; nt < 4; nt++) {
            int c = warp_n * 32 + nt * 8 + nc0;
            sm[r0 * 128 + ((c     + r0 * 8) & 127)] = acc[mt][nt][0];
            sm[r0 * 128 + ((c + 1 + r0 * 8) & 127)] = acc[mt][nt][1];
            sm[r1 * 128 + ((c     + r1 * 8) & 127)] = acc[mt][nt][2];
            sm[r1 * 128 + ((c + 1 + r1 * 8) & 127)] = acc[mt][nt][3];
        }
    }
}
__device__ __forceinline__ float sm_at(const float* sm, int r, int c) {
    return sm[r * 128 + ((c + r * 8) & 127)];
}

// EPI: 0 = plain fp32 C+bias.  2 = softmax(scale) -> fp16 split2.
//      4 = z-batched proj: z=0 headnorm->Ov(qp3); z=1 vp bf16 split3->Ov2 + sumsq->nsq.
template<int EPI, int DT>
__global__ void __launch_bounds__(256, 2)
wm_gemm_t(const void* __restrict__ Av, long aZ, const void* __restrict__ Bv, long bZ,
          float* __restrict__ C, long cZ, int ldc, int Ntot, int K2,
          const float* __restrict__ bias, const float* __restrict__ bias2,
          void* __restrict__ Ov, void* __restrict__ Ov2,
          float* __restrict__ nsq, const float* __restrict__ scl,
          int p0, int p1, int p2)
{
    extern __shared__ __align__(1024) char smem[];
    const uint32_t sb = smem_u32(smem);
    const int tid = threadIdx.x;
    const int wid = tid >> 5, lane = tid & 31;
    const int warp_m = wid >> 2, warp_n = wid & 3;

    const uint16_t* A = (const uint16_t*)Av + (long)blockIdx.z * aZ;
    const uint16_t* B = (const uint16_t*)Bv + (long)blockIdx.z * bZ;
    const int m0 = blockIdx.y * 128;
    const int n0 = blockIdx.x * 128;

    float acc[4][4][4];
    #pragma unroll
    for (int i = 0; i < 4; i++)
        #pragma unroll
        for (int j = 0; j < 4; j++)
            #pragma unroll
            for (int t = 0; t < 4; t++) acc[i][j][t] = 0.0f;

    gemm_mainloop<DT>(A, B, K2, sb, tid, lane, warp_m, warp_n, m0, n0, acc);

    if (EPI == 0) {
        float* Cw = C + (long)blockIdx.z * cZ;
        const int mrow = lane >> 2;
        const int ncol = (lane & 3) * 2;
        #pragma unroll
        for (int mt = 0; mt < 4; mt++) {
            int mbase = m0 + warp_m * 64 + mt * 16 + mrow;
            #pragma unroll
            for (int nt = 0; nt < 4; nt++) {
                int n = n0 + warp_n * 32 + nt * 8 + ncol;
                if (n < Ntot) {
                    float b0 = bias ? bias[n] : 0.0f;
                    float b1 = bias ? bias[n + 1] : 0.0f;
                    float* c0 = Cw + (long)mbase * ldc + n;
                    float* c1 = Cw + (long)(mbase + 8) * ldc + n;
                    c0[0] = acc[mt][nt][0] + b0;
                    c0[1] = acc[mt][nt][1] + b1;
                    c1[0] = acc[mt][nt][2] + b0;
                    c1[1] = acc[mt][nt][3] + b1;
                }
            }
        }
        return;
    }

    float* sm = reinterpret_cast<float*>(smem);
    dump_acc(sm, warp_m, warp_n, lane, acc);
    __syncthreads();

    if (EPI == 4) {
        if (blockIdx.z == 0) {
            // per-head normalize (heads 2*bx, 2*bx+1) -> qp3 bf16 split3
            __nv_bfloat16* O = (__nv_bfloat16*)Ov;
            for (int r = wid; r < 128; r += 8) {
                int m = m0 + r;
                float v0a = sm_at(sm, r, lane)      + bias[n0 + lane];
                float v0b = sm_at(sm, r, lane + 32) + bias[n0 + lane + 32];
                float v1a = sm_at(sm, r, lane + 64) + bias[n0 + lane + 64];
                float v1b = sm_at(sm, r, lane + 96) + bias[n0 + lane + 96];
                float i0 = 1.0f / fmaxf(sqrtf(warpSum(v0a * v0a + v0b * v0b)), 1e-12f);
                float i1 = 1.0f / fmaxf(sqrtf(warpSum(v1a * v1a + v1b * v1b)), 1e-12f);
                __nv_bfloat16* q0 = O + ((long)(2 * blockIdx.x)     * BS + m) * 192;
                __nv_bfloat16* q1 = O + ((long)(2 * blockIdx.x + 1) * BS + m) * 192;
                put_split3bf(q0, lane,      64, v0a * i0);
                put_split3bf(q0, lane + 32, 64, v0b * i0);
                put_split3bf(q1, lane,      64, v1a * i1);
                put_split3bf(q1, lane + 32, 64, v1b * i1);
            }
        } else {
            // vp (unnormalized) -> bf16 split3 + per-(row,xblock) sumsq partial
            __nv_bfloat16* O = (__nv_bfloat16*)Ov2;
            for (int r = wid; r < 128; r += 8) {
                int m = m0 + r;
                float v0 = sm_at(sm, r, lane)      + bias2[n0 + lane];
                float v1 = sm_at(sm, r, lane + 32) + bias2[n0 + lane + 32];
                float v2 = sm_at(sm, r, lane + 64) + bias2[n0 + lane + 64];
                float v3 = sm_at(sm, r, lane + 96) + bias2[n0 + lane + 96];
                float sq = warpSum(v0 * v0 + v1 * v1 + v2 * v2 + v3 * v3);
                if (lane == 0) nsq[(long)m * 4 + blockIdx.x] = sq;
                __nv_bfloat16* base = O + (long)m * 1536 + n0;
                put_split3bf(base, lane,      512, v0);
                put_split3bf(base, lane + 32, 512, v1);
                put_split3bf(base, lane + 64, 512, v2);
                put_split3bf(base, lane + 96, 512, v3);
            }
        }
    } else {  // EPI == 2: softmax over cols 0..111 with optional row scale, fp16 split2
        __half* O = (__half*)Ov;
        for (int r = wid; r < 128; r += 8) {
            int m = m0 + r;
            float rs = RADIUS * (scl ? scl[m] : 1.0f);
            float v[4];
            #pragma unroll
            for (int i = 0; i < 4; i++) {
                int c = lane + 32 * i;
                v[i] = (c < 112) ? rs * sm_at(sm, r, c) : -1e30f;
            }
            float mx = warpMax(fmaxf(fmaxf(v[0], v[1]), fmaxf(v[2], v[3])));
            float s = 0.0f;
            #pragma unroll
            for (int i = 0; i < 4; i++) {
                int c = lane + 32 * i;
                v[i] = (c < 112) ? __expf(v[i] - mx) : 0.0f;
                s += v[i];
            }
            float inv = 1.0f / warpSum(s);
            __half* base = O + (long)m * p0 + (p2 ? (int)blockIdx.z * p2 : 0);
            #pragma unroll
            for (int i = 0; i < 4; i++) {
                int c = lane + 32 * i;
                if (p2) {
                    if (c < 112) put_split2h(base, c, p1, v[i] * inv);
                } else {
                    if (c < 128) put_split2h(base, c, p1, (c < 112) ? v[i] * inv : 0.0f);
                }
            }
        }
    }
}

// ---------------- split fp32 -> bf16 triple (z selects input) ----------------
__global__ void split3_kernel(const float* __restrict__ X0, const float* __restrict__ X1,
                              int lda, __nv_bfloat16* __restrict__ Y, long yZ,
                              int Min, int Kin, int Kout, int isA)
{
    int k = blockIdx.x * 256 + threadIdx.x;
    if (k >= Kout) return;
    int m = blockIdx.y;
    const float* X = blockIdx.z ? X1 : X0;
    __nv_bfloat16* Yz = Y + (long)blockIdx.z * yZ + (long)m * 3 * Kout;
    float x = (m < Min && k < Kin) ? X[(long)m * lda + k] : 0.0f;
    __nv_bfloat16 h = __float2bfloat16(x);
    __nv_bfloat16 l = __float2bfloat16(x - __bfloat162float(h));
    Yz[k] = h;
    if (isA) { Yz[Kout + k] = l; Yz[2 * Kout + k] = h; }
    else     { Yz[Kout + k] = h; Yz[2 * Kout + k] = l; }
}

// ---------------- fused prep kernels ----------------
__global__ void normkey_split_kernel(const float* __restrict__ keyp,
                                     __nv_bfloat16* __restrict__ keyn3)
{
    int row = blockIdx.x * 8 + (threadIdx.x >> 5);
    int lane = threadIdx.x & 31;
    int h = row >> 7, s = row & 127;
    __nv_bfloat16* base = keyn3 + ((long)h * 128 + s) * 192;
    if (s < 112) {
        const float* p = keyp + ((long)h * 112 + s) * 64;
        float x0 = p[lane], x1 = p[lane + 32];
        float inv = 1.0f / fmaxf(sqrtf(warpSum(x0 * x0 + x1 * x1)), 1e-12f);
        float a = x0 * inv, b = x1 * inv;
        __nv_bfloat16 h0 = __float2bfloat16(a);
        __nv_bfloat16 l0 = __float2bfloat16(a - __bfloat162float(h0));
        __nv_bfloat16 h1 = __float2bfloat16(b);
        __nv_bfloat16 l1 = __float2bfloat16(b - __bfloat162float(h1));
        base[lane] = h0;       base[lane + 32] = h1;
        base[64 + lane] = h0;  base[96 + lane] = h1;
        base[128 + lane] = l0; base[160 + lane] = l1;
    } else {
        __nv_bfloat16 z = __float2bfloat16(0.0f);
        #pragma unroll
        for (int i = 0; i < 6; i++) base[lane + i * 32] = z;
    }
}

__global__ void normval_split_kernel(const float* __restrict__ valp,
                                     float* __restrict__ vnorm,
                                     __nv_bfloat16* __restrict__ vnorm3)
{
    __shared__ float sh[8];
    int row = blockIdx.x, t = threadIdx.x;
    __nv_bfloat16* base = vnorm3 + (long)row * 1536;
    if (row < 112) {
        const float* p = valp + (size_t)row * 512;
        float x0 = p[t], x1 = p[t + 256];
        float inv = 1.0f / fmaxf(sqrtf(blockSum256(x0 * x0 + x1 * x1, sh)), 1e-12f);
        float a = x0 * inv, b = x1 * inv;
        vnorm[(size_t)row * 512 + t] = a;
        vnorm[(size_t)row * 512 + t + 256] = b;
        __nv_bfloat16 h0 = __float2bfloat16(a);
        __nv_bfloat16 l0 = __float2bfloat16(a - __bfloat162float(h0));
        __nv_bfloat16 h1 = __float2bfloat16(b);
        __nv_bfloat16 l1 = __float2bfloat16(b - __bfloat162float(h1));
        base[t] = h0;        base[t + 256] = h1;
        base[512 + t] = h0;  base[768 + t] = h1;
        base[1024 + t] = l0; base[1280 + t] = l1;
    } else {
        __nv_bfloat16 z = __float2bfloat16(0.0f);
        base[t] = z;        base[t + 256] = z;
        base[512 + t] = z;  base[768 + t] = z;
        base[1024 + t] = z; base[1280 + t] = z;
    }
}

__global__ void transpose_split2_kernel(const float* __restrict__ valp,
                                        __half* __restrict__ dst)
{
    int d = blockIdx.x;
    int s = threadIdx.x;
    float x = (s < 112) ? valp[(long)s * 512 + d] : 0.0f;
    __half h = __float2half(x);
    __half* base = dst + (long)d * 256;
    base[s] = h; base[128 + s] = h;
}

// fold 4 sumsq partials -> 1/||row||
__global__ void rownorm_kernel(const float* __restrict__ nsq, float* __restrict__ invn)
{
    int m = blockIdx.x * 256 + threadIdx.x;
    if (m < BS) {
        float s = nsq[(long)m * 4] + nsq[(long)m * 4 + 1]
                + nsq[(long)m * 4 + 2] + nsq[(long)m * 4 + 3];
        invn[m] = 1.0f / fmaxf(sqrtf(s), 1e-12f);
    }
}

// ---------------- SIMT SGEMM (+ optional fp16 [hi|hi] secondary output) ----------------
__global__ void sgemm_tn(const float* __restrict__ A, int lda, int aZ,
                         const float* __restrict__ B, int ldb, int bZ,
                         float* __restrict__ C, int ldc, int cZ,
                         int M, int N, int K, const float* __restrict__ bias,
                         __half* __restrict__ C2, int ld2, int dup2)
{
    __shared__ __align__(16) float As[16][64];
    __shared__ __align__(16) float Bs[16][64];
    A += (size_t)blockIdx.z * aZ;
    B += (size_t)blockIdx.z * bZ;
    C += (size_t)blockIdx.z * cZ;
    const int n0g = blockIdx.z * N;
    const int m0 = blockIdx.y * 64, n0 = blockIdx.x * 64;
    const int tid = threadIdx.x;
    const int tx = tid & 15, ty = tid >> 4;
    const int lr = tid >> 2, lk = (tid & 3) * 4;
    float acc[4][4];
    #pragma unroll
    for (int i = 0; i < 4; i++)
        #pragma unroll
        for (int j = 0; j < 4; j++) acc[i][j] = 0.0f;
    const int am = m0 + lr, bn = n0 + lr;
    for (int k0 = 0; k0 < K; k0 += 16) {
        float a4[4], b4[4];
        #pragma unroll
        for (int j = 0; j < 4; j++) {
            int kk = k0 + lk + j;
            a4[j] = (am < M && kk < K) ? A[(size_t)am * lda + kk] : 0.0f;
            b4[j] = (bn < N && kk < K) ? B[(size_t)bn * ldb + kk] : 0.0f;
        }
        __syncthreads();
        #pragma unroll
        for (int j = 0; j < 4; j++) { As[lk + j][lr] = a4[j]; Bs[lk + j][lr] = b4[j]; }
        __syncthreads();
        #pragma unroll
        for (int kk = 0; kk < 16; kk++) {
            float4 ra = *reinterpret_cast<const float4*>(&As[kk][ty * 4]);
            float4 rb = *reinterpret_cast<const float4*>(&Bs[kk][tx * 4]);
            float aa[4] = {ra.x, ra.y, ra.z, ra.w};
            float bb[4] = {rb.x, rb.y, rb.z, rb.w};
            #pragma unroll
            for (int i = 0; i < 4; i++)
                #pragma unroll
                for (int j = 0; j < 4; j++) acc[i][j] = fmaf(aa[i], bb[j], acc[i][j]);
        }
    }
    #pragma unroll
    for (int i = 0; i < 4; i++) {
        int m = m0 + ty * 4 + i;
        if (m >= M) continue;
        #pragma unroll
        for (int j = 0; j < 4; j++) {
            int n = n0 + tx * 4 + j;
            if (n < N) {
                float v = acc[i][j];
                if (bias) v += bias[n];
                C[(size_t)m * ldc + n] = v;
                if (C2) {
                    __half h = __float2half(v);
                    __half* p2 = C2 + (size_t)m * ld2 + n0g + n;
                    p2[0] = h; p2[dup2] = h;
                }
            }
        }
    }
}

// ---------------- remaining elementwise ----------------
__global__ void layernorm512_kernel(float* __restrict__ x, const float* __restrict__ g,
                                    const float* __restrict__ b)
{
    __shared__ float sh[8];
    int row = blockIdx.x, t = threadIdx.x;
    float* p = x + (size_t)row * 512;
    float x0 = p[t], x1 = p[t + 256];
    float mu = blockSum256(x0 + x1, sh) * (1.0f / 512.0f);
    float d0 = x0 - mu, d1 = x1 - mu;
    float var = blockSum256(d0 * d0 + d1 * d1, sh) * (1.0f / 512.0f);
    float inv = rsqrtf(var + 1e-5f);
    p[t]       = d0 * inv * g[t]       + b[t];
    p[t + 256] = d1 * inv * g[t + 256] + b[t + 256];
}

__global__ void recon_ln_kernel(float* __restrict__ ar, const float* __restrict__ v,
                                float* __restrict__ rl, const float* __restrict__ g,
                                const float* __restrict__ b)
{
    __shared__ float sh[8];
    int row = blockIdx.x, t = threadIdx.x;
    float* p = ar + (size_t)row * 512;
    const float* w = v + (size_t)row * 512;
    float x0 = p[t], x1 = p[t + 256], y0 = w[t], y1 = w[t + 256];
    float dot = blockSum256(x0 * y0 + x1 * y1, sh);
    float na  = blockSum256(x0 * x0 + x1 * x1, sh);
    float nv  = blockSum256(y0 * y0 + y1 * y1, sh);
    if (t == 0)
        rl[row] = fabsf(1.0f - dot / fmaxf(sqrtf(na) * sqrtf(nv), 1e-8f));
    float mu = blockSum256(x0 + x1, sh) * (1.0f / 512.0f);
    float d0 = x0 - mu, d1 = x1 - mu;
    float var = blockSum256(d0 * d0 + d1 * d1, sh) * (1.0f / 512.0f);
    float inv = rsqrtf(var + 1e-5f);
    p[t]       = d0 * inv * g[t]       + b[t];
    p[t + 256] = d1 * inv * g[t + 256] + b[t + 256];
}

__global__ void reduce_recon_kernel(const float* __restrict__ rl, float* __restrict__ out)
{
    __shared__ float sh[8];
    float acc = 0.0f;
    for (int i = threadIdx.x; i < BS; i += 256) acc += rl[i];
    float tot = blockSum256(acc, sh);
    if (threadIdx.x == 0) out[0] = tot / (float)BS;
}

__global__ void contrastive_kernel(const float* __restrict__ G, float* __restrict__ out)
{
    __shared__ float sh[8];
    float acc = 0.0f;
    for (int idx = threadIdx.x; idx < NSLOT * NSLOT; idx += 256) {
        int i = idx / NSLOT, j = idx % NSLOT;
        float e = (i == j) ? 1.0f : 0.0f;
        acc += fabsf(e - G[idx]);
    }
    float tot = blockSum256(acc, sh);
    if (threadIdx.x == 0) out[0] = tot * 0.01f;
}

// ---------------- launch ----------------
extern "C" void kernel_launch(void* const* d_in, const int* in_sizes, int n_in,
                              void* d_out, int out_size)
{
    const float* query = (const float*)d_in[0];
    const float* value = (const float*)d_in[1];
    const float* keyp  = (const float*)d_in[2];
    const float* valp  = (const float*)d_in[3];
    const float* q_w   = (const float*)d_in[4];
    const float* q_b   = (const float*)d_in[5];
    const float* v_w   = (const float*)d_in[6];
    const float* v_b   = (const float*)d_in[7];
    const float* out_w = (const float*)d_in[8];
    const float* out_b = (const float*)d_in[9];
    const float* n2_g  = (const float*)d_in[10];
    const float* n2_b  = (const float*)d_in[11];
    const float* n3_g  = (const float*)d_in[12];
    const float* n3_b  = (const float*)d_in[13];

    float* out_fpred = (float*)d_out;
    float* out_frec  = out_fpred + (size_t)BS * DIMO;
    float* out_scal  = out_frec + (size_t)BS * DIMO;

    float *vnorm, *wfT, *gram, *rl, *nsq, *invn;
    cudaGetSymbolAddress((void**)&vnorm, g_vnorm);
    cudaGetSymbolAddress((void**)&wfT, g_wfT);
    cudaGetSymbolAddress((void**)&gram, g_gram);
    cudaGetSymbolAddress((void**)&rl, g_rl);
    cudaGetSymbolAddress((void**)&nsq, g_nsq);
    cudaGetSymbolAddress((void**)&invn, g_invn);

    __nv_bfloat16 *qv3, *qvw3, *qp3, *vp3, *keyn3, *vnorm3;
    cudaGetSymbolAddress((void**)&qv3, g_qv3);
    cudaGetSymbolAddress((void**)&qvw3, g_qvw3);
    cudaGetSymbolAddress((void**)&qp3, g_qp3);
    cudaGetSymbolAddress((void**)&vp3, g_vp3);
    cudaGetSymbolAddress((void**)&keyn3, g_keyn3);
    cudaGetSymbolAddress((void**)&vnorm3, g_vnorm3);

    __half *ka2, *va2, *wf2, *vpT2;
    cudaGetSymbolAddress((void**)&ka2, g_ka2);
    cudaGetSymbolAddress((void**)&va2, g_va2);
    cudaGetSymbolAddress((void**)&wf2, g_wf2);
    cudaGetSymbolAddress((void**)&vpT2, g_vpT2);

    cudaFuncSetAttribute(wm_gemm_t<4,0>, cudaFuncAttributeMaxDynamicSharedMemorySize, WM_SMEM);
    cudaFuncSetAttribute(wm_gemm_t<2,0>, cudaFuncAttributeMaxDynamicSharedMemorySize, WM_SMEM);
    cudaFuncSetAttribute(wm_gemm_t<0,1>, cudaFuncAttributeMaxDynamicSharedMemorySize, WM_SMEM);

    // ---- input splits (z-batched: query|value, q_w|v_w) ----
    split3_kernel<<<dim3(2, BS, 2), 256>>>(query, value, DIM, qv3, (long)BS * 1536,
                                           BS, DIM, DIM, 1);
    split3_kernel<<<dim3(2, 512, 2), 256>>>(q_w, v_w, DIM, qvw3, (long)512 * 1536,
                                            512, DIM, DIM, 0);
    normkey_split_kernel<<<128, 256>>>(keyp, keyn3);

    // ---- batched q+v projection (z=0: headnorm->qp3, z=1: vp split3 + sumsq) ----
    wm_gemm_t<4,0><<<dim3(4, 128, 2), 256, WM_SMEM>>>(
        qv3, (long)BS * 1536, qvw3, (long)512 * 1536,
        nullptr, 0, 512, 512, 1536, q_b, v_b, qp3, vp3, nsq, nullptr, 0, 0, 0);
    rownorm_kernel<<<BS / 256, 256>>>(nsq, invn);

    // ---- weight prep (independent of proj) ----
    normval_split_kernel<<<128, 256>>>(valp, vnorm, vnorm3);
    sgemm_tn<<<dim3(2, 8, NHEAD), 256>>>(out_w, NHEAD * DIMM, DIMM, valp, DIMM, 0,
                                         wfT, NHEAD * NSLOT, NSLOT, DIMO, NSLOT, DIMM,
                                         nullptr, wf2, 1792, 896);
    transpose_split2_kernel<<<512, 128>>>(valp, vpT2);

    // ---- key_sim + softmax -> ka2 (fp16 split2) ----
    wm_gemm_t<2,0><<<dim3(1, 128, NHEAD), 256, WM_SMEM>>>(
        qp3, (long)BS * 192, keyn3, 128L * 192,
        nullptr, 0, 0, 128, 192, nullptr, nullptr, ka2, nullptr, nullptr, nullptr,
        1792, 896, 112);

    // ---- att = key_addr @ wfold^T + out_b (fp16 GEMM) ----
    wm_gemm_t<0,1><<<dim3(4, 128, 1), 256, WM_SMEM>>>(
        ka2, 0, wf2, 0, out_fpred, 0, 512, 512, 1792, out_b, nullptr,
        nullptr, nullptr, nullptr, nullptr, 0, 0, 0);
    layernorm512_kernel<<<BS, 256>>>(out_fpred, n2_g, n2_b);

    // ---- v path: value_sim (scaled by 1/||vp||) + softmax -> va2 ----
    wm_gemm_t<2,0><<<dim3(1, 128, 1), 256, WM_SMEM>>>(
        vp3, 0, vnorm3, 0, nullptr, 0, 0, 128, 1536, nullptr, nullptr,
        va2, nullptr, nullptr, invn, 256, 128, 0);
    wm_gemm_t<0,1><<<dim3(4, 128, 1), 256, WM_SMEM>>>(
        va2, 0, vpT2, 0, out_frec, 0, 512, 512, 256, nullptr, nullptr,
        nullptr, nullptr, nullptr, nullptr, 0, 0, 0);
    recon_ln_kernel<<<BS, 256>>>(out_frec, value, rl, n3_g, n3_b);
    reduce_recon_kernel<<<1, 256>>>(rl, out_scal);

    // ---- contrastive ----
    sgemm_tn<<<dim3(2, 2, 1), 256>>>(vnorm, DIMM, 0, vnorm, DIMM, 0, gram, NSLOT, 0,
                                     NSLOT, NSLOT, DIMM, nullptr, nullptr, 0, 0);
    contrastive_kernel<<<1, 256>>>(gram, out_scal + 1);
}

// round 17
// speedup vs baseline: 1.1014x; 1.1014x over previous
#include <cuda_runtime.h>
#include <cuda_bf16.h>
#include <cuda_fp16.h>
#include <math.h>
#include <stdint.h>

// Problem constants
#define BSZ   32
#define SEQ   512
#define BS    (BSZ*SEQ)      // 16384
#define DIM   512
#define NHEAD 8
#define NSLOT 112
#define DIMQ  64
#define DIMM  512
#define DIMO  512
#define RADIUS 16.0f

// ---------------- static scratch ----------------
__device__ float g_vnorm[NSLOT * DIMM];
__device__ float g_wfT  [DIMO * (NHEAD*NSLOT)];
__device__ float g_gram [NSLOT * NSLOT];
__device__ float g_rl   [BS];
__device__ float g_nsq  [BS * 4];      // per-(row,xblock) sumsq partials of vp
__device__ float g_invn [BS];          // 1/||vp_row||

// bf16 split-3 buffers (sim path)
__device__ __nv_bfloat16 g_qv3  [(size_t)2 * BS * 1536];
__device__ __nv_bfloat16 g_qvw3 [(size_t)2 * 512 * 1536];
__device__ __nv_bfloat16 g_qp3  [(size_t)NHEAD * BS * 192];
__device__ __nv_bfloat16 g_vp3  [(size_t)BS * 1536];
__device__ __nv_bfloat16 g_keyn3[(size_t)NHEAD * 128 * 192];
__device__ __nv_bfloat16 g_vnorm3[(size_t)128 * 1536];

// fp16 hi-only buffers (post-softmax path)
__device__ __half g_ka2 [(size_t)BS * 896];    // key_addr hi
__device__ __half g_va2 [(size_t)BS * 128];    // value_addr hi (112 pad)
__device__ __half g_wf2 [(size_t)512 * 896];   // folded weight hi
__device__ __half g_vpT2[(size_t)512 * 128];   // value_param^T hi (112 pad)

// ---------------- PTX helpers ----------------
__device__ __forceinline__ uint32_t smem_u32(const void* p) {
    uint32_t a;
    asm("{ .reg .u64 t; cvta.to.shared.u64 t, %1; cvt.u32.u64 %0, t; }" : "=r"(a) : "l"(p));
    return a;
}
__device__ __forceinline__ void cp_async16(uint32_t dst, const void* src) {
    asm volatile("cp.async.cg.shared.global [%0], [%1], 16;\n" :: "r"(dst), "l"(src));
}
#define CP_COMMIT() asm volatile("cp.async.commit_group;\n" ::)
#define CP_WAIT(N)  asm volatile("cp.async.wait_group %0;\n" :: "n"(N))

__device__ __forceinline__ void ldsm_x4(uint32_t& r0, uint32_t& r1, uint32_t& r2,
                                        uint32_t& r3, uint32_t addr) {
    asm volatile("ldmatrix.sync.aligned.m8n8.x4.shared.b16 {%0,%1,%2,%3}, [%4];"
                 : "=r"(r0), "=r"(r1), "=r"(r2), "=r"(r3) : "r"(addr));
}
__device__ __forceinline__ void mma_bf16(float* c, uint32_t a0, uint32_t a1,
                                         uint32_t a2, uint32_t a3,
                                         uint32_t b0, uint32_t b1) {
    asm volatile(
        "mma.sync.aligned.m16n8k16.row.col.f32.bf16.bf16.f32 "
        "{%0,%1,%2,%3}, {%4,%5,%6,%7}, {%8,%9}, {%0,%1,%2,%3};"
        : "+f"(c[0]), "+f"(c[1]), "+f"(c[2]), "+f"(c[3])
        : "r"(a0), "r"(a1), "r"(a2), "r"(a3), "r"(b0), "r"(b1));
}
__device__ __forceinline__ void mma_fp16(float* c, uint32_t a0, uint32_t a1,
                                         uint32_t a2, uint32_t a3,
                                         uint32_t b0, uint32_t b1) {
    asm volatile(
        "mma.sync.aligned.m16n8k16.row.col.f32.f16.f16.f32 "
        "{%0,%1,%2,%3}, {%4,%5,%6,%7}, {%8,%9}, {%0,%1,%2,%3};"
        : "+f"(c[0]), "+f"(c[1]), "+f"(c[2]), "+f"(c[3])
        : "r"(a0), "r"(a1), "r"(a2), "r"(a3), "r"(b0), "r"(b1));
}
__device__ __forceinline__ uint32_t sw128(uint32_t off) {
    return off ^ ((off >> 3) & 0x70);
}
__device__ __forceinline__ float warpSum(float v) {
    #pragma unroll
    for (int o = 16; o > 0; o >>= 1) v += __shfl_xor_sync(0xffffffffu, v, o);
    return v;
}
__device__ __forceinline__ float warpMax(float v) {
    #pragma unroll
    for (int o = 16; o > 0; o >>= 1) v = fmaxf(v, __shfl_xor_sync(0xffffffffu, v, o));
    return v;
}
__device__ __forceinline__ float blockSum256(float v, float* sh) {
    int w = threadIdx.x >> 5, l = threadIdx.x & 31;
    float s = warpSum(v);
    if (l == 0) sh[w] = s;
    __syncthreads();
    float t = (threadIdx.x < 8) ? sh[threadIdx.x] : 0.0f;
    if (w == 0) { t = warpSum(t); if (l == 0) sh[0] = t; }
    __syncthreads();
    float r = sh[0];
    __syncthreads();
    return r;
}

// split stores
__device__ __forceinline__ void put_split3bf(__nv_bfloat16* base, int k, int seg, float x) {
    __nv_bfloat16 h = __float2bfloat16(x);
    __nv_bfloat16 l = __float2bfloat16(x - __bfloat162float(h));
    base[k] = h; base[seg + k] = l; base[2 * seg + k] = h;
}

// ---------------- warp-MMA GEMM mainloop (CTA 128x128, BK=64, double buffer) --------------
#define WM_SMEM 65536

template<int DT>
__device__ __forceinline__ void gemm_mainloop(
    const uint16_t* __restrict__ A, const uint16_t* __restrict__ B,
    int K2, uint32_t sb, int tid, int lane, int warp_m, int warp_n,
    int m0, int n0, float acc[4][4][4])
{
    const int NC = K2 >> 6;

    auto load_chunk = [&](int c, int bufi) {
        const uint16_t* Ap = A + (long)m0 * K2 + c * 64;
        const uint16_t* Bp = B + (long)n0 * K2 + c * 64;
        uint32_t sa = sb + bufi * 32768;
        uint32_t sB = sa + 16384;
        #pragma unroll
        for (int i = 0; i < 4; i++) {
            int idx = tid + i * 256;
            int row = idx >> 3, c16 = idx & 7;
            uint32_t sw = sw128(row * 128 + c16 * 16);
            cp_async16(sa + sw, Ap + (long)row * K2 + c16 * 8);
            cp_async16(sB + sw, Bp + (long)row * K2 + c16 * 8);
        }
    };

    load_chunk(0, 0);
    CP_COMMIT();

    for (int c = 0; c < NC; c++) {
        const int b = c & 1;
        if (c + 1 < NC) {
            load_chunk(c + 1, b ^ 1);
            CP_COMMIT();
            CP_WAIT(1);
        } else {
            CP_WAIT(0);
        }
        __syncthreads();

        const uint32_t sa = sb + b * 32768;
        const uint32_t sB = sa + 16384;

        #pragma unroll
        for (int ks = 0; ks < 4; ks++) {
            uint32_t a[4][4];
            #pragma unroll
            for (int mt = 0; mt < 4; mt++) {
                int row = warp_m * 64 + mt * 16 + (lane & 15);
                uint32_t off = (uint32_t)row * 128 + ks * 32 + (lane >> 4) * 16;
                ldsm_x4(a[mt][0], a[mt][1], a[mt][2], a[mt][3], sa + sw128(off));
            }
            uint32_t bf[4][2];
            #pragma unroll
            for (int p = 0; p < 2; p++) {
                int tile_id = lane >> 3;
                int nsub = tile_id >> 1, kch = tile_id & 1;
                int row = warp_n * 32 + p * 16 + nsub * 8 + (lane & 7);
                uint32_t off = (uint32_t)row * 128 + ks * 32 + kch * 16;
                uint32_t r0, r1, r2, r3;
                ldsm_x4(r0, r1, r2, r3, sB + sw128(off));
                bf[p * 2 + 0][0] = r0; bf[p * 2 + 0][1] = r1;
                bf[p * 2 + 1][0] = r2; bf[p * 2 + 1][1] = r3;
            }
            #pragma unroll
            for (int mt = 0; mt < 4; mt++)
                #pragma unroll
                for (int nt = 0; nt < 4; nt++) {
                    if (DT == 0)
                        mma_bf16(acc[mt][nt], a[mt][0], a[mt][1], a[mt][2], a[mt][3],
                                 bf[nt][0], bf[nt][1]);
                    else
                        mma_fp16(acc[mt][nt], a[mt][0], a[mt][1], a[mt][2], a[mt][3],
                                 bf[nt][0], bf[nt][1]);
                }
        }
        __syncthreads();
    }
}

// dump acc to smem fp32 tile [128][128] with +8*row column skew
__device__ __forceinline__ void dump_acc(float* sm, int warp_m, int warp_n, int lane,
                                         float acc[4][4][4])
{
    const int mrow = lane >> 2, nc0 = (lane & 3) * 2;
    #pragma unroll
    for (int mt = 0; mt < 4; mt++) {
        int r0 = warp_m * 64 + mt * 16 + mrow;
        int r1 = r0 + 8;
        #pragma unroll
        for (int nt = 0; nt < 4; nt++) {
            int c = warp_n * 32 + nt * 8 + nc0;
            sm[r0 * 128 + ((c     + r0 * 8) & 127)] = acc[mt][nt][0];
            sm[r0 * 128 + ((c + 1 + r0 * 8) & 127)] = acc[mt][nt][1];
            sm[r1 * 128 + ((c     + r1 * 8) & 127)] = acc[mt][nt][2];
            sm[r1 * 128 + ((c + 1 + r1 * 8) & 127)] = acc[mt][nt][3];
        }
    }
}
__device__ __forceinline__ float sm_at(const float* sm, int r, int c) {
    return sm[r * 128 + ((c + r * 8) & 127)];
}

// EPI: 0 = plain fp32 C+bias.  2 = softmax(scale) -> fp16 hi store.
//      4 = z-batched proj: z=0 headnorm->Ov(qp3); z=1 vp bf16 split3->Ov2 + sumsq->nsq.
template<int EPI, int DT>
__global__ void __launch_bounds__(256, 2)
wm_gemm_t(const void* __restrict__ Av, long aZ, const void* __restrict__ Bv, long bZ,
          float* __restrict__ C, long cZ, int ldc, int Ntot, int K2,
          const float* __restrict__ bias, const float* __restrict__ bias2,
          void* __restrict__ Ov, void* __restrict__ Ov2,
          float* __restrict__ nsq, const float* __restrict__ scl,
          int p0, int p2)
{
    extern __shared__ __align__(1024) char smem[];
    const uint32_t sb = smem_u32(smem);
    const int tid = threadIdx.x;
    const int wid = tid >> 5, lane = tid & 31;
    const int warp_m = wid >> 2, warp_n = wid & 3;

    const uint16_t* A = (const uint16_t*)Av + (long)blockIdx.z * aZ;
    const uint16_t* B = (const uint16_t*)Bv + (long)blockIdx.z * bZ;
    const int m0 = blockIdx.y * 128;
    const int n0 = blockIdx.x * 128;

    float acc[4][4][4];
    #pragma unroll
    for (int i = 0; i < 4; i++)
        #pragma unroll
        for (int j = 0; j < 4; j++)
            #pragma unroll
            for (int t = 0; t < 4; t++) acc[i][j][t] = 0.0f;

    gemm_mainloop<DT>(A, B, K2, sb, tid, lane, warp_m, warp_n, m0, n0, acc);

    if (EPI == 0) {
        float* Cw = C + (long)blockIdx.z * cZ;
        const int mrow = lane >> 2;
        const int ncol = (lane & 3) * 2;
        #pragma unroll
        for (int mt = 0; mt < 4; mt++) {
            int mbase = m0 + warp_m * 64 + mt * 16 + mrow;
            #pragma unroll
            for (int nt = 0; nt < 4; nt++) {
                int n = n0 + warp_n * 32 + nt * 8 + ncol;
                if (n < Ntot) {
                    float b0 = bias ? bias[n] : 0.0f;
                    float b1 = bias ? bias[n + 1] : 0.0f;
                    float* c0 = Cw + (long)mbase * ldc + n;
                    float* c1 = Cw + (long)(mbase + 8) * ldc + n;
                    c0[0] = acc[mt][nt][0] + b0;
                    c0[1] = acc[mt][nt][1] + b1;
                    c1[0] = acc[mt][nt][2] + b0;
                    c1[1] = acc[mt][nt][3] + b1;
                }
            }
        }
        return;
    }

    float* sm = reinterpret_cast<float*>(smem);
    dump_acc(sm, warp_m, warp_n, lane, acc);
    __syncthreads();

    if (EPI == 4) {
        if (blockIdx.z == 0) {
            // per-head normalize (heads 2*bx, 2*bx+1) -> qp3 bf16 split3
            __nv_bfloat16* O = (__nv_bfloat16*)Ov;
            for (int r = wid; r < 128; r += 8) {
                int m = m0 + r;
                float v0a = sm_at(sm, r, lane)      + bias[n0 + lane];
                float v0b = sm_at(sm, r, lane + 32) + bias[n0 + lane + 32];
                float v1a = sm_at(sm, r, lane + 64) + bias[n0 + lane + 64];
                float v1b = sm_at(sm, r, lane + 96) + bias[n0 + lane + 96];
                float i0 = 1.0f / fmaxf(sqrtf(warpSum(v0a * v0a + v0b * v0b)), 1e-12f);
                float i1 = 1.0f / fmaxf(sqrtf(warpSum(v1a * v1a + v1b * v1b)), 1e-12f);
                __nv_bfloat16* q0 = O + ((long)(2 * blockIdx.x)     * BS + m) * 192;
                __nv_bfloat16* q1 = O + ((long)(2 * blockIdx.x + 1) * BS + m) * 192;
                put_split3bf(q0, lane,      64, v0a * i0);
                put_split3bf(q0, lane + 32, 64, v0b * i0);
                put_split3bf(q1, lane,      64, v1a * i1);
                put_split3bf(q1, lane + 32, 64, v1b * i1);
            }
        } else {
            // vp (unnormalized) -> bf16 split3 + per-(row,xblock) sumsq partial
            __nv_bfloat16* O = (__nv_bfloat16*)Ov2;
            for (int r = wid; r < 128; r += 8) {
                int m = m0 + r;
                float v0 = sm_at(sm, r, lane)      + bias2[n0 + lane];
                float v1 = sm_at(sm, r, lane + 32) + bias2[n0 + lane + 32];
                float v2 = sm_at(sm, r, lane + 64) + bias2[n0 + lane + 64];
                float v3 = sm_at(sm, r, lane + 96) + bias2[n0 + lane + 96];
                float sq = warpSum(v0 * v0 + v1 * v1 + v2 * v2 + v3 * v3);
                if (lane == 0) nsq[(long)m * 4 + blockIdx.x] = sq;
                __nv_bfloat16* base = O + (long)m * 1536 + n0;
                put_split3bf(base, lane,      512, v0);
                put_split3bf(base, lane + 32, 512, v1);
                put_split3bf(base, lane + 64, 512, v2);
                put_split3bf(base, lane + 96, 512, v3);
            }
        }
    } else {  // EPI == 2: softmax over cols 0..111 with optional row scale, fp16 hi store
        __half* O = (__half*)Ov;
        for (int r = wid; r < 128; r += 8) {
            int m = m0 + r;
            float rs = RADIUS * (scl ? scl[m] : 1.0f);
            float v[4];
            #pragma unroll
            for (int i = 0; i < 4; i++) {
                int c = lane + 32 * i;
                v[i] = (c < 112) ? rs * sm_at(sm, r, c) : -1e30f;
            }
            float mx = warpMax(fmaxf(fmaxf(v[0], v[1]), fmaxf(v[2], v[3])));
            float s = 0.0f;
            #pragma unroll
            for (int i = 0; i < 4; i++) {
                int c = lane + 32 * i;
                v[i] = (c < 112) ? __expf(v[i] - mx) : 0.0f;
                s += v[i];
            }
            float inv = 1.0f / warpSum(s);
            __half* base = O + (long)m * p0 + (p2 ? (int)blockIdx.z * p2 : 0);
            #pragma unroll
            for (int i = 0; i < 4; i++) {
                int c = lane + 32 * i;
                if (p2) {                       // key_sim: only 112 valid cols
                    if (c < 112) base[c] = __float2half(v[i] * inv);
                } else {                        // value_sim: pad to 128 with zeros
                    if (c < 128) base[c] = __float2half((c < 112) ? v[i] * inv : 0.0f);
                }
            }
        }
    }
}

// ---------------- split fp32 -> bf16 triple (z selects input) ----------------
__global__ void split3_kernel(const float* __restrict__ X0, const float* __restrict__ X1,
                              int lda, __nv_bfloat16* __restrict__ Y, long yZ,
                              int Min, int Kin, int Kout, int isA)
{
    int k = blockIdx.x * 256 + threadIdx.x;
    if (k >= Kout) return;
    int m = blockIdx.y;
    const float* X = blockIdx.z ? X1 : X0;
    __nv_bfloat16* Yz = Y + (long)blockIdx.z * yZ + (long)m * 3 * Kout;
    float x = (m < Min && k < Kin) ? X[(long)m * lda + k] : 0.0f;
    __nv_bfloat16 h = __float2bfloat16(x);
    __nv_bfloat16 l = __float2bfloat16(x - __bfloat162float(h));
    Yz[k] = h;
    if (isA) { Yz[Kout + k] = l; Yz[2 * Kout + k] = h; }
    else     { Yz[Kout + k] = h; Yz[2 * Kout + k] = l; }
}

// ---------------- fused prep kernels ----------------
__global__ void normkey_split_kernel(const float* __restrict__ keyp,
                                     __nv_bfloat16* __restrict__ keyn3)
{
    int row = blockIdx.x * 8 + (threadIdx.x >> 5);
    int lane = threadIdx.x & 31;
    int h = row >> 7, s = row & 127;
    __nv_bfloat16* base = keyn3 + ((long)h * 128 + s) * 192;
    if (s < 112) {
        const float* p = keyp + ((long)h * 112 + s) * 64;
        float x0 = p[lane], x1 = p[lane + 32];
        float inv = 1.0f / fmaxf(sqrtf(warpSum(x0 * x0 + x1 * x1)), 1e-12f);
        float a = x0 * inv, b = x1 * inv;
        __nv_bfloat16 h0 = __float2bfloat16(a);
        __nv_bfloat16 l0 = __float2bfloat16(a - __bfloat162float(h0));
        __nv_bfloat16 h1 = __float2bfloat16(b);
        __nv_bfloat16 l1 = __float2bfloat16(b - __bfloat162float(h1));
        base[lane] = h0;       base[lane + 32] = h1;
        base[64 + lane] = h0;  base[96 + lane] = h1;
        base[128 + lane] = l0; base[160 + lane] = l1;
    } else {
        __nv_bfloat16 z = __float2bfloat16(0.0f);
        #pragma unroll
        for (int i = 0; i < 6; i++) base[lane + i * 32] = z;
    }
}

__global__ void normval_split_kernel(const float* __restrict__ valp,
                                     float* __restrict__ vnorm,
                                     __nv_bfloat16* __restrict__ vnorm3)
{
    __shared__ float sh[8];
    int row = blockIdx.x, t = threadIdx.x;
    __nv_bfloat16* base = vnorm3 + (long)row * 1536;
    if (row < 112) {
        const float* p = valp + (size_t)row * 512;
        float x0 = p[t], x1 = p[t + 256];
        float inv = 1.0f / fmaxf(sqrtf(blockSum256(x0 * x0 + x1 * x1, sh)), 1e-12f);
        float a = x0 * inv, b = x1 * inv;
        vnorm[(size_t)row * 512 + t] = a;
        vnorm[(size_t)row * 512 + t + 256] = b;
        __nv_bfloat16 h0 = __float2bfloat16(a);
        __nv_bfloat16 l0 = __float2bfloat16(a - __bfloat162float(h0));
        __nv_bfloat16 h1 = __float2bfloat16(b);
        __nv_bfloat16 l1 = __float2bfloat16(b - __bfloat162float(h1));
        base[t] = h0;        base[t + 256] = h1;
        base[512 + t] = h0;  base[768 + t] = h1;
        base[1024 + t] = l0; base[1280 + t] = l1;
    } else {
        __nv_bfloat16 z = __float2bfloat16(0.0f);
        base[t] = z;        base[t + 256] = z;
        base[512 + t] = z;  base[768 + t] = z;
        base[1024 + t] = z; base[1280 + t] = z;
    }
}

__global__ void transpose_split2_kernel(const float* __restrict__ valp,
                                        __half* __restrict__ dst)
{
    int d = blockIdx.x;
    int s = threadIdx.x;
    float x = (s < 112) ? valp[(long)s * 512 + d] : 0.0f;
    dst[(long)d * 128 + s] = __float2half(x);
}

// fold 4 sumsq partials -> 1/||row||
__global__ void rownorm_kernel(const float* __restrict__ nsq, float* __restrict__ invn)
{
    int m = blockIdx.x * 256 + threadIdx.x;
    if (m < BS) {
        float s = nsq[(long)m * 4] + nsq[(long)m * 4 + 1]
                + nsq[(long)m * 4 + 2] + nsq[(long)m * 4 + 3];
        invn[m] = 1.0f / fmaxf(sqrtf(s), 1e-12f);
    }
}

// ---------------- SIMT SGEMM (+ optional fp16 hi secondary output) ----------------
__global__ void sgemm_tn(const float* __restrict__ A, int lda, int aZ,
                         const float* __restrict__ B, int ldb, int bZ,
                         float* __restrict__ C, int ldc, int cZ,
                         int M, int N, int K, const float* __restrict__ bias,
                         __half* __restrict__ C2, int ld2)
{
    __shared__ __align__(16) float As[16][64];
    __shared__ __align__(16) float Bs[16][64];
    A += (size_t)blockIdx.z * aZ;
    B += (size_t)blockIdx.z * bZ;
    C += (size_t)blockIdx.z * cZ;
    const int n0g = blockIdx.z * N;
    const int m0 = blockIdx.y * 64, n0 = blockIdx.x * 64;
    const int tid = threadIdx.x;
    const int tx = tid & 15, ty = tid >> 4;
    const int lr = tid >> 2, lk = (tid & 3) * 4;
    float acc[4][4];
    #pragma unroll
    for (int i = 0; i < 4; i++)
        #pragma unroll
        for (int j = 0; j < 4; j++) acc[i][j] = 0.0f;
    const int am = m0 + lr, bn = n0 + lr;
    for (int k0 = 0; k0 < K; k0 += 16) {
        float a4[4], b4[4];
        #pragma unroll
        for (int j = 0; j < 4; j++) {
            int kk = k0 + lk + j;
            a4[j] = (am < M && kk < K) ? A[(size_t)am * lda + kk] : 0.0f;
            b4[j] = (bn < N && kk < K) ? B[(size_t)bn * ldb + kk] : 0.0f;
        }
        __syncthreads();
        #pragma unroll
        for (int j = 0; j < 4; j++) { As[lk + j][lr] = a4[j]; Bs[lk + j][lr] = b4[j]; }
        __syncthreads();
        #pragma unroll
        for (int kk = 0; kk < 16; kk++) {
            float4 ra = *reinterpret_cast<const float4*>(&As[kk][ty * 4]);
            float4 rb = *reinterpret_cast<const float4*>(&Bs[kk][tx * 4]);
            float aa[4] = {ra.x, ra.y, ra.z, ra.w};
            float bb[4] = {rb.x, rb.y, rb.z, rb.w};
            #pragma unroll
            for (int i = 0; i < 4; i++)
                #pragma unroll
                for (int j = 0; j < 4; j++) acc[i][j] = fmaf(aa[i], bb[j], acc[i][j]);
        }
    }
    #pragma unroll
    for (int i = 0; i < 4; i++) {
        int m = m0 + ty * 4 + i;
        if (m >= M) continue;
        #pragma unroll
        for (int j = 0; j < 4; j++) {
            int n = n0 + tx * 4 + j;
            if (n < N) {
                float v = acc[i][j];
                if (bias) v += bias[n];
                C[(size_t)m * ldc + n] = v;
                if (C2) C2[(size_t)m * ld2 + n0g + n] = __float2half(v);
            }
        }
    }
}

// ---------------- remaining elementwise ----------------
__global__ void layernorm512_kernel(float* __restrict__ x, const float* __restrict__ g,
                                    const float* __restrict__ b)
{
    __shared__ float sh[8];
    int row = blockIdx.x, t = threadIdx.x;
    float* p = x + (size_t)row * 512;
    float x0 = p[t], x1 = p[t + 256];
    float mu = blockSum256(x0 + x1, sh) * (1.0f / 512.0f);
    float d0 = x0 - mu, d1 = x1 - mu;
    float var = blockSum256(d0 * d0 + d1 * d1, sh) * (1.0f / 512.0f);
    float inv = rsqrtf(var + 1e-5f);
    p[t]       = d0 * inv * g[t]       + b[t];
    p[t + 256] = d1 * inv * g[t + 256] + b[t + 256];
}

__global__ void recon_ln_kernel(float* __restrict__ ar, const float* __restrict__ v,
                                float* __restrict__ rl, const float* __restrict__ g,
                                const float* __restrict__ b)
{
    __shared__ float sh[8];
    int row = blockIdx.x, t = threadIdx.x;
    float* p = ar + (size_t)row * 512;
    const float* w = v + (size_t)row * 512;
    float x0 = p[t], x1 = p[t + 256], y0 = w[t], y1 = w[t + 256];
    float dot = blockSum256(x0 * y0 + x1 * y1, sh);
    float na  = blockSum256(x0 * x0 + x1 * x1, sh);
    float nv  = blockSum256(y0 * y0 + y1 * y1, sh);
    if (t == 0)
        rl[row] = fabsf(1.0f - dot / fmaxf(sqrtf(na) * sqrtf(nv), 1e-8f));
    float mu = blockSum256(x0 + x1, sh) * (1.0f / 512.0f);
    float d0 = x0 - mu, d1 = x1 - mu;
    float var = blockSum256(d0 * d0 + d1 * d1, sh) * (1.0f / 512.0f);
    float inv = rsqrtf(var + 1e-5f);
    p[t]       = d0 * inv * g[t]       + b[t];
    p[t + 256] = d1 * inv * g[t + 256] + b[t + 256];
}

__global__ void reduce_recon_kernel(const float* __restrict__ rl, float* __restrict__ out)
{
    __shared__ float sh[8];
    float acc = 0.0f;
    for (int i = threadIdx.x; i < BS; i += 256) acc += rl[i];
    float tot = blockSum256(acc, sh);
    if (threadIdx.x == 0) out[0] = tot / (float)BS;
}

__global__ void contrastive_kernel(const float* __restrict__ G, float* __restrict__ out)
{
    __shared__ float sh[8];
    float acc = 0.0f;
    for (int idx = threadIdx.x; idx < NSLOT * NSLOT; idx += 256) {
        int i = idx / NSLOT, j = idx % NSLOT;
        float e = (i == j) ? 1.0f : 0.0f;
        acc += fabsf(e - G[idx]);
    }
    float tot = blockSum256(acc, sh);
    if (threadIdx.x == 0) out[0] = tot * 0.01f;
}

// ---------------- launch ----------------
extern "C" void kernel_launch(void* const* d_in, const int* in_sizes, int n_in,
                              void* d_out, int out_size)
{
    const float* query = (const float*)d_in[0];
    const float* value = (const float*)d_in[1];
    const float* keyp  = (const float*)d_in[2];
    const float* valp  = (const float*)d_in[3];
    const float* q_w   = (const float*)d_in[4];
    const float* q_b   = (const float*)d_in[5];
    const float* v_w   = (const float*)d_in[6];
    const float* v_b   = (const float*)d_in[7];
    const float* out_w = (const float*)d_in[8];
    const float* out_b = (const float*)d_in[9];
    const float* n2_g  = (const float*)d_in[10];
    const float* n2_b  = (const float*)d_in[11];
    const float* n3_g  = (const float*)d_in[12];
    const float* n3_b  = (const float*)d_in[13];

    float* out_fpred = (float*)d_out;
    float* out_frec  = out_fpred + (size_t)BS * DIMO;
    float* out_scal  = out_frec + (size_t)BS * DIMO;

    float *vnorm, *wfT, *gram, *rl, *nsq, *invn;
    cudaGetSymbolAddress((void**)&vnorm, g_vnorm);
    cudaGetSymbolAddress((void**)&wfT, g_wfT);
    cudaGetSymbolAddress((void**)&gram, g_gram);
    cudaGetSymbolAddress((void**)&rl, g_rl);
    cudaGetSymbolAddress((void**)&nsq, g_nsq);
    cudaGetSymbolAddress((void**)&invn, g_invn);

    __nv_bfloat16 *qv3, *qvw3, *qp3, *vp3, *keyn3, *vnorm3;
    cudaGetSymbolAddress((void**)&qv3, g_qv3);
    cudaGetSymbolAddress((void**)&qvw3, g_qvw3);
    cudaGetSymbolAddress((void**)&qp3, g_qp3);
    cudaGetSymbolAddress((void**)&vp3, g_vp3);
    cudaGetSymbolAddress((void**)&keyn3, g_keyn3);
    cudaGetSymbolAddress((void**)&vnorm3, g_vnorm3);

    __half *ka2, *va2, *wf2, *vpT2;
    cudaGetSymbolAddress((void**)&ka2, g_ka2);
    cudaGetSymbolAddress((void**)&va2, g_va2);
    cudaGetSymbolAddress((void**)&wf2, g_wf2);
    cudaGetSymbolAddress((void**)&vpT2, g_vpT2);

    cudaFuncSetAttribute(wm_gemm_t<4,0>, cudaFuncAttributeMaxDynamicSharedMemorySize, WM_SMEM);
    cudaFuncSetAttribute(wm_gemm_t<2,0>, cudaFuncAttributeMaxDynamicSharedMemorySize, WM_SMEM);
    cudaFuncSetAttribute(wm_gemm_t<0,1>, cudaFuncAttributeMaxDynamicSharedMemorySize, WM_SMEM);

    // ---- input splits (z-batched: query|value, q_w|v_w) ----
    split3_kernel<<<dim3(2, BS, 2), 256>>>(query, value, DIM, qv3, (long)BS * 1536,
                                           BS, DIM, DIM, 1);
    split3_kernel<<<dim3(2, 512, 2), 256>>>(q_w, v_w, DIM, qvw3, (long)512 * 1536,
                                            512, DIM, DIM, 0);
    normkey_split_kernel<<<128, 256>>>(keyp, keyn3);

    // ---- batched q+v projection (z=0: headnorm->qp3, z=1: vp split3 + sumsq) ----
    wm_gemm_t<4,0><<<dim3(4, 128, 2), 256, WM_SMEM>>>(
        qv3, (long)BS * 1536, qvw3, (long)512 * 1536,
        nullptr, 0, 512, 512, 1536, q_b, v_b, qp3, vp3, nsq, nullptr, 0, 0);
    rownorm_kernel<<<BS / 256, 256>>>(nsq, invn);

    // ---- weight prep (independent of proj) ----
    normval_split_kernel<<<128, 256>>>(valp, vnorm, vnorm3);
    sgemm_tn<<<dim3(2, 8, NHEAD), 256>>>(out_w, NHEAD * DIMM, DIMM, valp, DIMM, 0,
                                         wfT, NHEAD * NSLOT, NSLOT, DIMO, NSLOT, DIMM,
                                         nullptr, wf2, 896);
    transpose_split2_kernel<<<512, 128>>>(valp, vpT2);

    // ---- key_sim + softmax -> ka2 (fp16 hi) ----
    wm_gemm_t<2,0><<<dim3(1, 128, NHEAD), 256, WM_SMEM>>>(
        qp3, (long)BS * 192, keyn3, 128L * 192,
        nullptr, 0, 0, 128, 192, nullptr, nullptr, ka2, nullptr, nullptr, nullptr,
        896, 112);

    // ---- att = key_addr @ wfold^T + out_b (fp16 GEMM, K=896) ----
    wm_gemm_t<0,1><<<dim3(4, 128, 1), 256, WM_SMEM>>>(
        ka2, 0, wf2, 0, out_fpred, 0, 512, 512, 896, out_b, nullptr,
        nullptr, nullptr, nullptr, nullptr, 0, 0);
    layernorm512_kernel<<<BS, 256>>>(out_fpred, n2_g, n2_b);

    // ---- v path: value_sim (scaled by 1/||vp||) + softmax -> va2 (fp16 hi) ----
    wm_gemm_t<2,0><<<dim3(1, 128, 1), 256, WM_SMEM>>>(
        vp3, 0, vnorm3, 0, nullptr, 0, 0, 128, 1536, nullptr, nullptr,
        va2, nullptr, nullptr, invn, 128, 0);
    wm_gemm_t<0,1><<<dim3(4, 128, 1), 256, WM_SMEM>>>(
        va2, 0, vpT2, 0, out_frec, 0, 512, 512, 128, nullptr, nullptr,
        nullptr, nullptr, nullptr, nullptr, 0, 0);
    recon_ln_kernel<<<BS, 256>>>(out_frec, value, rl, n3_g, n3_b);
    reduce_recon_kernel<<<1, 256>>>(rl, out_scal);

    // ---- contrastive ----
    sgemm_tn<<<dim3(2, 2, 1), 256>>>(vnorm, DIMM, 0, vnorm, DIMM, 0, gram, NSLOT, 0,
                                     NSLOT, NSLOT, DIMM, nullptr, nullptr, 0);
    contrastive_kernel<<<1, 256>>>(gram, out_scal + 1);
}